// round 17
// baseline (speedup 1.0000x reference)
#include <cuda_runtime.h>
#include <cuda_bf16.h>
#include <math.h>
#include <stdint.h>

#define NMAT 4
#define NSUB 4096
#define DIM 64
#define KTOP 20
#define NROWS 8192
#define DELTA 0.008f
#define FULLM 0xffffffffu
#define CAND 48            // candidates per quarter-row

// device global scratch (no allocation allowed)
__device__ float g_v1[NMAT][NSUB][DIM];
__device__ float g_v2[NMAT][NSUB][DIM];
__device__ __nv_bfloat16 g_v1b[NMAT][NSUB][DIM];
__device__ __nv_bfloat16 g_v2b[NMAT][NSUB][DIM];
__device__ float          g_cm[NROWS][256];       // sampled 16-col maxima
__device__ float          g_cval[NROWS][4 * CAND];
__device__ unsigned short g_ccol[NROWS][4 * CAND];

__device__ __forceinline__ uint32_t smem_u32(const void* p) {
    uint32_t a;
    asm("{ .reg .u64 t; cvta.to.shared.u64 t, %1; cvt.u32.u64 %0, t; }" : "=r"(a) : "l"(p));
    return a;
}

// ---------------------------------------------------------------------------
// v = emb @ w + b (fp32) + bf16 copy
// ---------------------------------------------------------------------------
__global__ void compute_v_kernel(const float* __restrict__ emb1,
                                 const float* __restrict__ emb2,
                                 const float* __restrict__ w1,
                                 const float* __restrict__ w2,
                                 const float* __restrict__ b1,
                                 const float* __restrict__ b2) {
    int which = blockIdx.z;
    int k = blockIdx.y;
    int tile = blockIdx.x;
    const float* emb = which ? emb2 : emb1;
    const float* w   = which ? w2   : w1;
    const float* b   = which ? b2   : b1;
    float* vout            = which ? &g_v2[0][0][0]  : &g_v1[0][0][0];
    __nv_bfloat16* voutb   = which ? &g_v2b[0][0][0] : &g_v1b[0][0][0];

    __shared__ float semb[64 * 65];
    __shared__ float sw[64 * 64];
    __shared__ float sb[64];

    int tid = threadIdx.x;
    for (int t = tid; t < 4096; t += 256) {
        int r = t >> 6, e = t & 63;
        semb[r * 65 + e] = emb[(size_t)(k * NSUB + tile * 64 + r) * 64 + e];
        sw[t] = w[k * 4096 + t];
    }
    if (tid < 64) sb[tid] = b[k * 64 + tid];
    __syncthreads();

    int nl = tid & 63, q = tid >> 6;
    float acc[16];
#pragma unroll
    for (int d = 0; d < 16; d++) acc[d] = 0.f;

#pragma unroll 4
    for (int e = 0; e < 64; e++) {
        float a = semb[nl * 65 + e];
#pragma unroll
        for (int jj = 0; jj < 4; jj++) {
            float4 wv = *(const float4*)&sw[e * 64 + q * 16 + jj * 4];
            acc[jj * 4 + 0] += a * wv.x;
            acc[jj * 4 + 1] += a * wv.y;
            acc[jj * 4 + 2] += a * wv.z;
            acc[jj * 4 + 3] += a * wv.w;
        }
    }

    size_t rowoff = (size_t)(k * NSUB + tile * 64 + nl) * 64;
    float* orow = vout + rowoff;
    __nv_bfloat16* orowb = voutb + rowoff;
#pragma unroll
    for (int dd = 0; dd < 16; dd++) {
        int d = q * 16 + dd;
        float v = acc[dd] + sb[d];
        orow[d]  = v;
        orowb[d] = __float2bfloat16(v);
    }
}

// ---------------------------------------------------------------------------
// HMMA plumbing. 256 threads, 64-row tiles. NEW warp layout:
// warp w: rp = w&1 (rows rp*32..+31, two m16 tiles), cq = w>>1 (cols cq*16..+15,
// two n8 tiles). 4 ldmatrix.x4 + 16 mma per warp per 64-col chunk (B LDSM
// halved vs rowband layout; B smem redundancy 2x not 4x).
// B: 4-stage cp.async ring, 3-deep prefetch.
// grid = (xq: 4 [colmodule j = xq>>1, quarter qq = xq&1], rowtile: 128).
// ---------------------------------------------------------------------------
#define OFF_A  0
#define OFF_B  9216
#define SM_AB  46080            // A(9216) + 4 B stages (4x9216)

// acc[rt][nt][4]: rt = m16 row tile (rows rp*32+rt*16), nt = n8 col tile
#define MMA_CHUNK22(acc, af, bbuf, cq, lane)                                    \
    do {                                                                        \
        _Pragma("unroll")                                                       \
        for (int nt = 0; nt < 2; nt++) {                                        \
            uint32_t ba = (bbuf) + ((cq) * 16 + nt * 8 + ((lane) & 7)) * 144    \
                          + ((lane) >> 3) * 16;                                 \
            uint32_t b0, b1, b2, b3, b4, b5, b6, b7;                            \
            asm volatile("ldmatrix.sync.aligned.m8n8.x4.shared.b16 {%0,%1,%2,%3}, [%4];" \
                         : "=r"(b0), "=r"(b1), "=r"(b2), "=r"(b3) : "r"(ba));   \
            asm volatile("ldmatrix.sync.aligned.m8n8.x4.shared.b16 {%0,%1,%2,%3}, [%4];" \
                         : "=r"(b4), "=r"(b5), "=r"(b6), "=r"(b7) : "r"(ba + 64)); \
            _Pragma("unroll")                                                   \
            for (int rt = 0; rt < 2; rt++) {                                    \
                asm volatile("mma.sync.aligned.m16n8k16.row.col.f32.bf16.bf16.f32 " \
                             "{%0,%1,%2,%3}, {%4,%5,%6,%7}, {%8,%9}, {%0,%1,%2,%3};" \
                             : "+f"(acc[rt][nt][0]), "+f"(acc[rt][nt][1]),      \
                               "+f"(acc[rt][nt][2]), "+f"(acc[rt][nt][3])       \
                             : "r"(af[rt][0][0]), "r"(af[rt][0][1]),            \
                               "r"(af[rt][0][2]), "r"(af[rt][0][3]),            \
                               "r"(b0), "r"(b1));                               \
                asm volatile("mma.sync.aligned.m16n8k16.row.col.f32.bf16.bf16.f32 " \
                             "{%0,%1,%2,%3}, {%4,%5,%6,%7}, {%8,%9}, {%0,%1,%2,%3};" \
                             : "+f"(acc[rt][nt][0]), "+f"(acc[rt][nt][1]),      \
                               "+f"(acc[rt][nt][2]), "+f"(acc[rt][nt][3])       \
                             : "r"(af[rt][1][0]), "r"(af[rt][1][1]),            \
                               "r"(af[rt][1][2]), "r"(af[rt][1][3]),            \
                               "r"(b2), "r"(b3));                               \
                asm volatile("mma.sync.aligned.m16n8k16.row.col.f32.bf16.bf16.f32 " \
                             "{%0,%1,%2,%3}, {%4,%5,%6,%7}, {%8,%9}, {%0,%1,%2,%3};" \
                             : "+f"(acc[rt][nt][0]), "+f"(acc[rt][nt][1]),      \
                               "+f"(acc[rt][nt][2]), "+f"(acc[rt][nt][3])       \
                             : "r"(af[rt][2][0]), "r"(af[rt][2][1]),            \
                               "r"(af[rt][2][2]), "r"(af[rt][2][3]),            \
                               "r"(b4), "r"(b5));                               \
                asm volatile("mma.sync.aligned.m16n8k16.row.col.f32.bf16.bf16.f32 " \
                             "{%0,%1,%2,%3}, {%4,%5,%6,%7}, {%8,%9}, {%0,%1,%2,%3};" \
                             : "+f"(acc[rt][nt][0]), "+f"(acc[rt][nt][1]),      \
                               "+f"(acc[rt][nt][2]), "+f"(acc[rt][nt][3])       \
                             : "r"(af[rt][3][0]), "r"(af[rt][3][1]),            \
                               "r"(af[rt][3][2]), "r"(af[rt][3][3]),            \
                               "r"(b6), "r"(b7));                               \
            }                                                                   \
        }                                                                       \
    } while (0)

__device__ __forceinline__ void load_A(char* smem, int tid, int k, int nbase) {
    const int4* asrc = (const int4*)&g_v1b[k][nbase][0];
    for (int f = tid; f < 512; f += 256) {
        int r = f >> 3, q = f & 7;
        *(int4*)(smem + OFF_A + r * 144 + q * 16) = asrc[f];
    }
}

// 8KB B chunk (64 rows starting at row0): slot = ring slot 0..3
__device__ __forceinline__ void cp_async_B(uint32_t sbase, int tid, int k,
                                           int row0, int slot) {
    const int4* src = (const int4*)&g_v2b[k][row0][0];
#pragma unroll
    for (int f = tid; f < 512; f += 256) {
        int r = f >> 3, q = f & 7;
        uint32_t dst = sbase + OFF_B + slot * 9216 + r * 144 + q * 16;
        asm volatile("cp.async.cg.shared.global [%0], [%1], 16;" :: "r"(dst), "l"(src + f));
    }
    asm volatile("cp.async.commit_group;");
}

// A fragments: af[rt][ks][4], rows rp*32 + rt*16
__device__ __forceinline__ void preload_af2(uint32_t af[2][4][4], uint32_t sbase,
                                            int rp, int lane) {
#pragma unroll
    for (int rt = 0; rt < 2; rt++) {
        uint32_t abase = sbase + OFF_A + (rp * 32 + rt * 16 + (lane & 15)) * 144
                         + (lane >> 4) * 16;
#pragma unroll
        for (int ks = 0; ks < 4; ks++) {
            asm volatile("ldmatrix.sync.aligned.m8n8.x4.shared.b16 {%0,%1,%2,%3}, [%4];"
                         : "=r"(af[rt][ks][0]), "=r"(af[rt][ks][1]),
                           "=r"(af[rt][ks][2]), "=r"(af[rt][ks][3])
                         : "r"(abase + ks * 32));
        }
    }
}

// ---------------------------------------------------------------------------
// Pass 1: HMMA over EVEN 64-col chunks (half sample) + 16-col maxima
// + zero first half of this CTA's output slice.
// ---------------------------------------------------------------------------
__global__ void __launch_bounds__(256, 3) score1_kernel(float* __restrict__ out) {
    extern __shared__ char smem[];
    uint32_t sbase = smem_u32(smem);
    int tid = threadIdx.x, wid = tid >> 5, lane = tid & 31;
    int rp = wid & 1, cq = wid >> 1;
    int xq = blockIdx.x, rt2 = blockIdx.y;
    int j = xq >> 1, qq = xq & 1;
    int mod_i = rt2 >> 6;
    int k = mod_i * 2 + j;
    int nbase = (rt2 & 63) * 64;
    int rowg0 = rt2 * 64;
    int colbase = qq * 2048;
    int q4 = j * 2 + qq;

    float4* ob = (float4*)out + (size_t)(xq * 128 + rt2) * 32768;
    const float4 z4 = make_float4(0.f, 0.f, 0.f, 0.f);

    load_A(smem, tid, k, nbase);
    cp_async_B(sbase, tid, k, colbase + 0 * 128, 0);
    cp_async_B(sbase, tid, k, colbase + 1 * 128, 1);
    cp_async_B(sbase, tid, k, colbase + 2 * 128, 2);
    __syncthreads();

    uint32_t af[2][4][4];
    preload_af2(af, sbase, rp, lane);

    int lrow = rp * 32 + (lane >> 2);   // lane's base row within tile (rt adds 16)

    for (int cc = 0; cc < 16; cc++) {
        asm volatile("cp.async.wait_group 2;");
        __syncthreads();
        if (cc + 3 < 16) cp_async_B(sbase, tid, k, colbase + (cc + 3) * 128, (cc + 3) & 3);

        {   // fused zero: 1024 float4 / iter
            float4* zb = ob + cc * 1024;
#pragma unroll
            for (int f = tid; f < 1024; f += 256) zb[f] = z4;
        }

        uint32_t bbuf = sbase + OFF_B + (cc & 3) * 9216;
        float acc[2][2][4];
#pragma unroll
        for (int rt = 0; rt < 2; rt++)
#pragma unroll
            for (int nt = 0; nt < 2; nt++)
#pragma unroll
                for (int s = 0; s < 4; s++) acc[rt][nt][s] = 0.f;
        MMA_CHUNK22(acc, af, bbuf, cq, lane);

        // 16-col maxima per (rt, row-half)
#pragma unroll
        for (int rt = 0; rt < 2; rt++) {
            float mlo = fmaxf(fmaxf(acc[rt][0][0], acc[rt][0][1]),
                              fmaxf(acc[rt][1][0], acc[rt][1][1]));
            float mhi = fmaxf(fmaxf(acc[rt][0][2], acc[rt][0][3]),
                              fmaxf(acc[rt][1][2], acc[rt][1][3]));
            mlo = fmaxf(mlo, __shfl_xor_sync(FULLM, mlo, 1));
            mlo = fmaxf(mlo, __shfl_xor_sync(FULLM, mlo, 2));
            mhi = fmaxf(mhi, __shfl_xor_sync(FULLM, mhi, 1));
            mhi = fmaxf(mhi, __shfl_xor_sync(FULLM, mhi, 2));
            if ((lane & 3) == 0) {
                int cmi = q4 * 64 + cc * 4 + cq;
                g_cm[rowg0 + lrow + rt * 16][cmi]     = mlo;
                g_cm[rowg0 + lrow + rt * 16 + 8][cmi] = mhi;
            }
        }
    }
}

// ---------------------------------------------------------------------------
// Pass 2: prologue computes per-row T from g_cm (fused thr), then HMMA all
// 32 chunks + filter-append values > T + zero second half of output slice.
// smem: A+4B(46080) + sT 64*4 @46080 + fv @46336 + fc @58624 + cnt @64768.
// ---------------------------------------------------------------------------
#define OFF_ST 46080
#define OFF_FV 46336
#define OFF_FC 58624
#define OFF_CN 64768
#define SM2_TOTAL 65024

__global__ void __launch_bounds__(256, 3) score2_kernel(float* __restrict__ out) {
    extern __shared__ char smem[];
    uint32_t sbase = smem_u32(smem);
    int tid = threadIdx.x, wid = tid >> 5, lane = tid & 31;
    int rp = wid & 1, cq = wid >> 1;
    int xq = blockIdx.x, rt2 = blockIdx.y;
    int j = xq >> 1, qq = xq & 1;
    int mod_i = rt2 >> 6;
    int k = mod_i * 2 + j;
    int nbase = (rt2 & 63) * 64;
    int rowg0 = rt2 * 64;
    int colbase = qq * 2048;

    float* sT = (float*)(smem + OFF_ST);
    float* fv = (float*)(smem + OFF_FV);
    unsigned short* fc = (unsigned short*)(smem + OFF_FC);
    int* cnt = (int*)(smem + OFF_CN);
    if (tid < 64) cnt[tid] = 0;

    float4* ob = (float4*)out + (size_t)(xq * 128 + rt2) * 32768 + 16384;
    const float4 z4 = make_float4(0.f, 0.f, 0.f, 0.f);

    load_A(smem, tid, k, nbase);
    cp_async_B(sbase, tid, k, colbase + 0 * 64, 0);
    cp_async_B(sbase, tid, k, colbase + 1 * 64, 1);
    cp_async_B(sbase, tid, k, colbase + 2 * 64, 2);

    // fused thr: warp w computes T for rows w*8..w*8+7 (overlaps cp.async)
    for (int rr = 0; rr < 8; rr++) {
        int row = rowg0 + wid * 8 + rr;
        float a[8];
#pragma unroll
        for (int s = 0; s < 8; s++) a[s] = g_cm[row][lane + 32 * s];
        float last = -1e30f;
#pragma unroll
        for (int kk = 0; kk < KTOP; kk++) {
            float bv = a[0];
#pragma unroll
            for (int s = 1; s < 8; s++) bv = fmaxf(bv, a[s]);
#pragma unroll
            for (int off = 16; off > 0; off >>= 1)
                bv = fmaxf(bv, __shfl_xor_sync(FULLM, bv, off));
#pragma unroll
            for (int s = 0; s < 8; s++) a[s] = (a[s] == bv) ? -1e30f : a[s];
            last = bv;
        }
        if (lane == 0) sT[wid * 8 + rr] = last - DELTA;
    }
    __syncthreads();

    uint32_t af[2][4][4];
    preload_af2(af, sbase, rp, lane);

    int lrow = rp * 32 + (lane >> 2);
    float Tl[2], Th[2];
#pragma unroll
    for (int rt = 0; rt < 2; rt++) {
        Tl[rt] = sT[lrow + rt * 16];
        Th[rt] = sT[lrow + rt * 16 + 8];
    }
    int dcol = (lane & 3) * 2;
    int cbase = j * 4096 + colbase;

    for (int cc = 0; cc < 32; cc++) {
        asm volatile("cp.async.wait_group 2;");
        __syncthreads();
        if (cc + 3 < 32) cp_async_B(sbase, tid, k, colbase + (cc + 3) * 64, (cc + 3) & 3);

        {   // fused zero: 512 float4 / chunk
            float4* zb = ob + cc * 512;
#pragma unroll
            for (int f = tid; f < 512; f += 256) zb[f] = z4;
        }

        uint32_t bbuf = sbase + OFF_B + (cc & 3) * 9216;
        float acc[2][2][4];
#pragma unroll
        for (int rt = 0; rt < 2; rt++)
#pragma unroll
            for (int nt = 0; nt < 2; nt++)
#pragma unroll
                for (int s = 0; s < 4; s++) acc[rt][nt][s] = 0.f;
        MMA_CHUNK22(acc, af, bbuf, cq, lane);

#pragma unroll
        for (int rt = 0; rt < 2; rt++) {
            int r0 = lrow + rt * 16;
            int r1 = r0 + 8;
#pragma unroll
            for (int nt = 0; nt < 2; nt++) {
                int colb = cbase + cc * 64 + cq * 16 + nt * 8 + dcol;
                if (acc[rt][nt][0] > Tl[rt]) {
                    int p = atomicAdd(&cnt[r0], 1);
                    if (p < CAND) { fv[r0 * CAND + p] = acc[rt][nt][0];
                                    fc[r0 * CAND + p] = (unsigned short)colb; }
                }
                if (acc[rt][nt][1] > Tl[rt]) {
                    int p = atomicAdd(&cnt[r0], 1);
                    if (p < CAND) { fv[r0 * CAND + p] = acc[rt][nt][1];
                                    fc[r0 * CAND + p] = (unsigned short)(colb + 1); }
                }
                if (acc[rt][nt][2] > Th[rt]) {
                    int p = atomicAdd(&cnt[r1], 1);
                    if (p < CAND) { fv[r1 * CAND + p] = acc[rt][nt][2];
                                    fc[r1 * CAND + p] = (unsigned short)colb; }
                }
                if (acc[rt][nt][3] > Th[rt]) {
                    int p = atomicAdd(&cnt[r1], 1);
                    if (p < CAND) { fv[r1 * CAND + p] = acc[rt][nt][3];
                                    fc[r1 * CAND + p] = (unsigned short)(colb + 1); }
                }
            }
        }
    }
    __syncthreads();

    for (int t = tid; t < 64 * CAND; t += 256) {
        int r = t / CAND, i = t % CAND;
        int n = min(cnt[r], CAND);
        g_cval[rowg0 + r][xq * CAND + i] = (i < n) ? fv[t] : -1e30f;
        g_ccol[rowg0 + r][xq * CAND + i] = fc[t];
    }
}

// ---------------------------------------------------------------------------
// Merge: block = 8 rows, warp/row. 192 candidates (6/lane):
// pass-1 bf16 20th -> fp32 rescore of survivors -> pass-2 top-20 -> scatter.
// ---------------------------------------------------------------------------
__global__ void merge_rescore_kernel(float* __restrict__ out) {
    __shared__ float sv1[8][2][64];
    int tid = threadIdx.x;
    int w = tid >> 5, lane = tid & 31;
    int row = blockIdx.x * 8 + w;
    int mod_i = row >> 12, rloc = row & 4095;

    for (int t = lane; t < 128; t += 32) {
        int h = t >> 6, d = t & 63;
        sv1[w][h][d] = g_v1[mod_i * 2 + h][rloc][d];
    }
    __syncwarp();

    float wv[6]; int col[6];
#pragma unroll
    for (int s = 0; s < 6; s++) {
        int idx = lane * 6 + s;
        wv[s]  = g_cval[row][idx];
        col[s] = (int)g_ccol[row][idx];
    }

    float a0 = wv[0], a1 = wv[1], a2 = wv[2], a3 = wv[3], a4 = wv[4], a5 = wv[5];
    float thr = 0.f;
#pragma unroll
    for (int kk = 0; kk < KTOP; kk++) {
        float bv = fmaxf(fmaxf(fmaxf(a0, a1), fmaxf(a2, a3)), fmaxf(a4, a5));
#pragma unroll
        for (int off = 16; off > 0; off >>= 1)
            bv = fmaxf(bv, __shfl_xor_sync(FULLM, bv, off));
        a0 = (a0 == bv) ? -1e30f : a0;
        a1 = (a1 == bv) ? -1e30f : a1;
        a2 = (a2 == bv) ? -1e30f : a2;
        a3 = (a3 == bv) ? -1e30f : a3;
        a4 = (a4 == bv) ? -1e30f : a4;
        a5 = (a5 == bv) ? -1e30f : a5;
        thr = bv;
    }

    float rv[6];
#pragma unroll
    for (int s = 0; s < 6; s++) {
        if (wv[s] >= thr - DELTA) {
            int h = col[s] >> 12, cl = col[s] & 4095;
            const float4* v2c = (const float4*)&g_v2[mod_i * 2 + h][cl][0];
            const float4* v1c = (const float4*)&sv1[w][h][0];
            float acc = 0.f;
#pragma unroll
            for (int dd = 0; dd < 16; dd++) {
                float4 x = v1c[dd], y = v2c[dd];
                acc += x.x * y.x + x.y * y.y + x.z * y.z + x.w * y.w;
            }
            rv[s] = acc;
        } else {
            rv[s] = -1e30f;
        }
    }

#pragma unroll
    for (int kk = 0; kk < KTOP; kk++) {
        float bv = rv[0]; int bs = 0;
        if (rv[1] > bv) { bv = rv[1]; bs = 1; }
        if (rv[2] > bv) { bv = rv[2]; bs = 2; }
        if (rv[3] > bv) { bv = rv[3]; bs = 3; }
        if (rv[4] > bv) { bv = rv[4]; bs = 4; }
        if (rv[5] > bv) { bv = rv[5]; bs = 5; }
        int bc = col[bs];
        int bi = lane * 8 + bs;
#pragma unroll
        for (int off = 16; off > 0; off >>= 1) {
            float ov = __shfl_xor_sync(FULLM, bv, off);
            int   oc = __shfl_xor_sync(FULLM, bc, off);
            int   oi = __shfl_xor_sync(FULLM, bi, off);
            if (ov > bv || (ov == bv && oi < bi)) { bv = ov; bc = oc; bi = oi; }
        }
        if (lane == (bi >> 3)) rv[bi & 7] = -1e30f;
        if (lane == kk) {
            float t = (bv > 0.f) ? tanhf(3.0f * bv) : 0.f;
            out[(size_t)row * NROWS + bc] = t;
        }
    }
}

// ---------------------------------------------------------------------------
extern "C" void kernel_launch(void* const* d_in, const int* in_sizes, int n_in,
                              void* d_out, int out_size) {
    const float* emb1 = (const float*)d_in[1];
    const float* emb2 = (const float*)d_in[2];
    const float* w1   = (const float*)d_in[3];
    const float* w2   = (const float*)d_in[4];
    const float* b1   = (const float*)d_in[5];
    const float* b2   = (const float*)d_in[6];
    float* out = (float*)d_out;

    cudaFuncSetAttribute(score1_kernel,
                         cudaFuncAttributeMaxDynamicSharedMemorySize, SM_AB);
    cudaFuncSetAttribute(score2_kernel,
                         cudaFuncAttributeMaxDynamicSharedMemorySize, SM2_TOTAL);

    compute_v_kernel<<<dim3(64, NMAT, 2), 256>>>(emb1, emb2, w1, w2, b1, b2);
    score1_kernel<<<dim3(4, 128), 256, SM_AB>>>(out);
    score2_kernel<<<dim3(4, 128), 256, SM2_TOTAL>>>(out);
    merge_rescore_kernel<<<NROWS / 8, 256>>>(out);
}